// round 1
// baseline (speedup 1.0000x reference)
#include <cuda_runtime.h>
#include <cuda_bf16.h>
#include <cstddef>

// FlaxLinear per-irrep block linear:
//   out[b, off + w*D + i] = PW * sum_u W[u,w] * x[b, off + u*D + i]   (+ bias on D==1 block)
// Reformulated as GEMM with rows r=(b,i): C' = A' @ (PW*W), M'=B*D, N=512, K=512.
// Key trick: the k-tile across all i of one batch row is CONTIGUOUS in global
// memory (columns off+k0*D .. off+(k0+BK)*D), so A loads are coalesced float4;
// the (u,i) de-interleave happens while storing to SMEM.

static constexpr int MUL  = 512;
static constexpr int DIM  = 4608;   // 512*(1+3+5)
static constexpr int BATCH = 4096;
static constexpr float PW = 0.04419417382415922f;  // 512^-0.5

// D: irrep dim; BM: batch rows per block tile; TM: per-thread rows.
// Block tile: R = BM*D rows x BN=128 cols. 256 threads as 16x16, thread tile TM x 8.
template<int D, int BM, int TM>
__global__ __launch_bounds__(256) void irrep_linear_kernel(
    const float* __restrict__ x,
    const float* __restrict__ w,
    const float* __restrict__ bias,
    float* __restrict__ out,
    int off)
{
    constexpr int R  = BM * D;     // rows of C' tile
    constexpr int BN = 128;
    constexpr int BK = 16;
    constexpr int TN = 8;
    static_assert((R / TM) * (BN / TN) == 256, "thread layout");

    __shared__ float As[BK][R + 4];    // k-major: As[k][r_local]
    __shared__ float Bs[BK][BN + 4];   // Bs[k][w_local], pre-scaled by PW

    const int tid = threadIdx.x;
    const int tc  = tid & 15;          // 0..15 -> w direction
    const int tr  = tid >> 4;          // 0..15 -> row direction
    const int b0  = blockIdx.y * BM;
    const int w0  = blockIdx.x * BN;

    float acc[TM][TN];
    #pragma unroll
    for (int m = 0; m < TM; m++)
        #pragma unroll
        for (int n = 0; n < TN; n++)
            acc[m][n] = 0.0f;

    constexpr int VPR     = (BK * D) / 4;   // float4 per batch row per k-tile
    constexpr int TOTAL_V = BM * VPR;       // total A float4s per k-tile
    constexpr int BV      = (BK * BN) / 4;  // total B float4s per k-tile

    for (int k0 = 0; k0 < MUL; k0 += BK) {
        // ---- load A tile: contiguous BK*D floats per batch row, de-interleave to SMEM
        #pragma unroll 2
        for (int v = tid; v < TOTAL_V; v += 256) {
            const int bl = v / VPR;
            const int jv = v % VPR;
            const float4 val = *reinterpret_cast<const float4*>(
                x + (size_t)(b0 + bl) * DIM + off + k0 * D + jv * 4);
            const int j = jv * 4;
            const float vv[4] = {val.x, val.y, val.z, val.w};
            #pragma unroll
            for (int e = 0; e < 4; e++) {
                const int jj = j + e;
                As[jj / D][bl * D + (jj % D)] = vv[e];
            }
        }
        // ---- load B tile (weights, row-major [u][w]), fold in PW
        #pragma unroll 2
        for (int v = tid; v < BV; v += 256) {
            const int k  = v / (BN / 4);
            const int wv = v % (BN / 4);
            float4 val = *reinterpret_cast<const float4*>(
                w + (size_t)(k0 + k) * MUL + w0 + wv * 4);
            val.x *= PW; val.y *= PW; val.z *= PW; val.w *= PW;
            *reinterpret_cast<float4*>(&Bs[k][wv * 4]) = val;
        }
        __syncthreads();

        // ---- compute
        #pragma unroll
        for (int k = 0; k < BK; k++) {
            float ra[TM], rb[TN];
            #pragma unroll
            for (int m = 0; m < TM; m++) ra[m] = As[k][tr * TM + m];
            #pragma unroll
            for (int n = 0; n < TN; n++) rb[n] = Bs[k][tc * TN + n];
            #pragma unroll
            for (int m = 0; m < TM; m++)
                #pragma unroll
                for (int n = 0; n < TN; n++)
                    acc[m][n] = fmaf(ra[m], rb[n], acc[m][n]);
        }
        __syncthreads();
    }

    // ---- epilogue: r=(b,i) -> out[b*DIM + off + w*D + i]. All (w,i) of the tile are
    // written by this block, so the strided 4B stores fully cover sectors (L2 merges).
    #pragma unroll
    for (int m = 0; m < TM; m++) {
        const int r = tr * TM + m;
        const int b = b0 + r / D;
        const int i = r % D;
        float* orow = out + (size_t)b * DIM + off + i;
        #pragma unroll
        for (int n = 0; n < TN; n++) {
            const int wc = w0 + tc * TN + n;
            float v = acc[m][n];
            if (D == 1) v += bias[wc];   // bias only on scalar (0e) block
            orow[(size_t)wc * D] = v;
        }
    }
}

extern "C" void kernel_launch(void* const* d_in, const int* in_sizes, int n_in,
                              void* d_out, int out_size)
{
    const float* x  = (const float*)d_in[0];
    const float* w0 = (const float*)d_in[1];
    const float* w1 = (const float*)d_in[2];
    const float* w2 = (const float*)d_in[3];
    const float* b0 = (const float*)d_in[4];
    float* out = (float*)d_out;

    // Block 0: D=1, off=0.    M'=4096,  tiles: 4 x (4096/128)
    {
        dim3 grid(MUL / 128, BATCH / 128);
        irrep_linear_kernel<1, 128, 8><<<grid, 256>>>(x, w0, b0, out, 0);
    }
    // Block 1: D=3, off=512.  M'=12288, tiles: 4 x (4096/32), R=96
    {
        dim3 grid(MUL / 128, BATCH / 32);
        irrep_linear_kernel<3, 32, 6><<<grid, 256>>>(x, w1, b0, out, 512);
    }
    // Block 2: D=5, off=2048. M'=20480, tiles: 4 x (4096/32), R=160
    {
        dim3 grid(MUL / 128, BATCH / 32);
        irrep_linear_kernel<5, 32, 10><<<grid, 256>>>(x, w2, b0, out, 2048);
    }
}

// round 2
// speedup vs baseline: 3.0487x; 3.0487x over previous
#include <cuda_runtime.h>
#include <cuda_bf16.h>
#include <cstdint>
#include <cstddef>

// FlaxLinear per-irrep block linear on tensor cores (tf32 mma.sync):
//   out[b, off + w*D + i] = PW * sum_u W[u,w] * x[b, off + u*D + i]  (+bias on D==1)
// GEMM form with rows r=(b,i): C' = A' @ (PW*W), per-irrep M'=4096*D, N=K=512.
// A k-tile per batch row is a CONTIGUOUS span of BK*D floats -> coalesced float4
// loads; (u,i) de-interleave happens at the SMEM store. SMEM strides chosen with
// (stride % 32) == 8 so mma fragment LDS is bank-conflict-free.

static constexpr int MUL   = 512;
static constexpr int DIM   = 4608;
static constexpr int BATCH = 4096;
static constexpr float PW  = 0.04419417382415922f;  // 512^-0.5
static constexpr int BN = 128;
static constexpr int BK = 32;

__device__ __forceinline__ float to_tf32(float x) {
    asm("cvt.rna.tf32.f32 %0, %0;" : "+f"(x));
    return x;
}

__device__ __forceinline__ void mma_tf32(
    float& c0, float& c1, float& c2, float& c3,
    uint32_t a0, uint32_t a1, uint32_t a2, uint32_t a3,
    uint32_t b0, uint32_t b1)
{
    asm volatile(
        "mma.sync.aligned.m16n8k8.row.col.f32.tf32.tf32.f32 "
        "{%0,%1,%2,%3}, {%4,%5,%6,%7}, {%8,%9}, {%0,%1,%2,%3};"
        : "+f"(c0), "+f"(c1), "+f"(c2), "+f"(c3)
        : "r"(a0), "r"(a1), "r"(a2), "r"(a3), "r"(b0), "r"(b1));
}

// D: irrep dim; R: tile rows (= BM*D, multiple of 16); NWM x NWN = 8 warps.
template<int D, int R, int NWM, int NWN>
__global__ __launch_bounds__(256) void irrep_mma_kernel(
    const float* __restrict__ x,
    const float* __restrict__ w,
    const float* __restrict__ bias,
    float* __restrict__ out,
    int off)
{
    constexpr int BM    = R / D;
    constexpr int WM    = R / NWM;     // warp tile rows
    constexpr int WN    = BN / NWN;    // warp tile cols
    constexpr int MFRAG = WM / 16;
    constexpr int NFRAG = WN / 8;
    constexpr int LDA   = R + 8;       // (R+8)%32 == 8 for R in {96,128,160}
    constexpr int LDB   = BN + 8;      // 136 % 32 == 8
    static_assert(NWM * NWN == 8, "8 warps");
    static_assert(WM % 16 == 0 && WN % 8 == 0, "frag divisibility");

    __shared__ float As[BK][LDA];   // As[k][r_local], tf32-rounded
    __shared__ float Bs[BK][LDB];   // Bs[k][n_local], PW-scaled, tf32-rounded

    const int tid  = threadIdx.x;
    const int wid  = tid >> 5;
    const int lane = tid & 31;
    const int g    = lane >> 2;     // groupID  0..7
    const int tig  = lane & 3;      // thread-in-group 0..3
    const int wm   = wid % NWM;
    const int wn   = wid / NWM;
    const int b0   = blockIdx.y * BM;
    const int w0   = blockIdx.x * BN;

    float acc[MFRAG][NFRAG][4];
    #pragma unroll
    for (int m = 0; m < MFRAG; m++)
        #pragma unroll
        for (int n = 0; n < NFRAG; n++)
            #pragma unroll
            for (int e = 0; e < 4; e++)
                acc[m][n][e] = 0.0f;

    constexpr int VPR     = (BK * D) / 4;   // float4 per batch row per k-tile
    constexpr int TOTAL_V = BM * VPR;       // A float4s per k-tile (multiple of 256)
    constexpr int BV      = (BK * BN) / 4;  // B float4s per k-tile (= 1024)

    for (int k0 = 0; k0 < MUL; k0 += BK) {
        // ---- A: contiguous BK*D floats per batch row -> de-interleave to As[k][r]
        #pragma unroll
        for (int v = tid; v < TOTAL_V; v += 256) {
            const int bl = v / VPR;
            const int jv = v % VPR;
            const float4 val = *reinterpret_cast<const float4*>(
                x + (size_t)(b0 + bl) * DIM + off + k0 * D + jv * 4);
            const float vv[4] = {val.x, val.y, val.z, val.w};
            const int j = jv * 4;
            #pragma unroll
            for (int e = 0; e < 4; e++) {
                const int jj = j + e;
                As[jj / D][bl * D + (jj % D)] = to_tf32(vv[e]);
            }
        }
        // ---- B: weights row-major [u][w], fold PW, round to tf32
        #pragma unroll
        for (int v = tid; v < BV; v += 256) {
            const int k  = v >> 5;          // / (BN/4)
            const int nv = v & 31;
            const float4 val = *reinterpret_cast<const float4*>(
                w + (size_t)(k0 + k) * MUL + w0 + nv * 4);
            Bs[k][nv * 4 + 0] = to_tf32(val.x * PW);
            Bs[k][nv * 4 + 1] = to_tf32(val.y * PW);
            Bs[k][nv * 4 + 2] = to_tf32(val.z * PW);
            Bs[k][nv * 4 + 3] = to_tf32(val.w * PW);
        }
        __syncthreads();

        // ---- tensor-core compute: BK/8 k-steps
        #pragma unroll
        for (int kk = 0; kk < BK; kk += 8) {
            uint32_t afr[MFRAG][4];
            #pragma unroll
            for (int m = 0; m < MFRAG; m++) {
                const int rb = wm * WM + m * 16;
                afr[m][0] = __float_as_uint(As[kk + tig    ][rb + g    ]);
                afr[m][1] = __float_as_uint(As[kk + tig    ][rb + g + 8]);
                afr[m][2] = __float_as_uint(As[kk + tig + 4][rb + g    ]);
                afr[m][3] = __float_as_uint(As[kk + tig + 4][rb + g + 8]);
            }
            uint32_t bfr[NFRAG][2];
            #pragma unroll
            for (int n = 0; n < NFRAG; n++) {
                const int nb = wn * WN + n * 8;
                bfr[n][0] = __float_as_uint(Bs[kk + tig    ][nb + g]);
                bfr[n][1] = __float_as_uint(Bs[kk + tig + 4][nb + g]);
            }
            #pragma unroll
            for (int m = 0; m < MFRAG; m++)
                #pragma unroll
                for (int n = 0; n < NFRAG; n++)
                    mma_tf32(acc[m][n][0], acc[m][n][1], acc[m][n][2], acc[m][n][3],
                             afr[m][0], afr[m][1], afr[m][2], afr[m][3],
                             bfr[n][0], bfr[n][1]);
        }
        __syncthreads();
    }

    // ---- epilogue: c0,c1 at (row, 2*tig), (row, 2*tig+1); c2,c3 at row+8
    #pragma unroll
    for (int m = 0; m < MFRAG; m++) {
        #pragma unroll
        for (int half = 0; half < 2; half++) {
            const int row = wm * WM + m * 16 + g + half * 8;
            const int b   = b0 + row / D;
            const int i   = row % D;
            float* orow = out + (size_t)b * DIM + off + i;
            #pragma unroll
            for (int n = 0; n < NFRAG; n++) {
                const int col = wn * WN + n * 8 + 2 * tig;
                #pragma unroll
                for (int e = 0; e < 2; e++) {
                    const int wc = w0 + col + e;
                    float v = acc[m][n][half * 2 + e];
                    if (D == 1) v += bias[wc];
                    orow[(size_t)wc * D] = v;
                }
            }
        }
    }
}

extern "C" void kernel_launch(void* const* d_in, const int* in_sizes, int n_in,
                              void* d_out, int out_size)
{
    const float* x  = (const float*)d_in[0];
    const float* w0 = (const float*)d_in[1];
    const float* w1 = (const float*)d_in[2];
    const float* w2 = (const float*)d_in[3];
    const float* b0 = (const float*)d_in[4];
    float* out = (float*)d_out;

    // D=1: tile 128x128, warps 4x2 (WM=32, WN=64)
    {
        dim3 grid(MUL / BN, BATCH / 128);
        irrep_mma_kernel<1, 128, 4, 2><<<grid, 256>>>(x, w0, b0, out, 0);
    }
    // D=3: tile 96x128, warps 2x4 (WM=48, WN=32)
    {
        dim3 grid(MUL / BN, BATCH / 32);
        irrep_mma_kernel<3, 96, 2, 4><<<grid, 256>>>(x, w1, b0, out, 512);
    }
    // D=5: tile 160x128, warps 2x4 (WM=80, WN=32)
    {
        dim3 grid(MUL / BN, BATCH / 32);
        irrep_mma_kernel<5, 160, 2, 4><<<grid, 256>>>(x, w2, b0, out, 2048);
    }
}

// round 3
// speedup vs baseline: 3.5927x; 1.1785x over previous
#include <cuda_runtime.h>
#include <cstdint>
#include <cstddef>

// Fused e3nn-style per-irrep linear, tf32 mma.sync, cp.async double-buffered.
//   out[b, off + w*D + i] = PW * sum_u W[u,w] * x[b, off + u*D + i]  (+bias, D==1)
// GEMM rows r=(b,i). One launch covers all three irreps via linear block index.

static constexpr int MUL   = 512;
static constexpr int DIM   = 4608;
static constexpr int BATCH = 4096;
static constexpr float PW  = 0.04419417382415922f;  // 512^-0.5
static constexpr int BN  = 128;
static constexpr int BK  = 16;
static constexpr int LDK = BK + 4;   // 20: (rb+g)*20+tig is a lane-bijection mod 32
static constexpr int LDB = BN + 8;   // 136: (kk+tig)*136+nb+g likewise

static constexpr int ASZ_MAX = 128 * LDK;          // largest R is 128 (D=1)
static constexpr int BSZ     = BK * LDB;
static constexpr int SM_FLOATS = 2 * ASZ_MAX + 2 * BSZ;   // 9472 floats = 37,888 B

__device__ __forceinline__ float to_tf32(float x) {
    asm("cvt.rna.tf32.f32 %0, %0;" : "+f"(x));
    return x;
}
__device__ __forceinline__ void cp_async16(uint32_t s, const void* g) {
    asm volatile("cp.async.cg.shared.global [%0], [%1], 16;" :: "r"(s), "l"(g));
}
__device__ __forceinline__ void cp_async4(uint32_t s, const void* g) {
    asm volatile("cp.async.ca.shared.global [%0], [%1], 4;" :: "r"(s), "l"(g));
}
__device__ __forceinline__ void cp_commit() {
    asm volatile("cp.async.commit_group;" ::: "memory");
}
__device__ __forceinline__ void cp_wait1() {
    asm volatile("cp.async.wait_group 1;" ::: "memory");
}

__device__ __forceinline__ void mma_tf32(
    float& c0, float& c1, float& c2, float& c3,
    uint32_t a0, uint32_t a1, uint32_t a2, uint32_t a3,
    uint32_t b0, uint32_t b1)
{
    asm volatile(
        "mma.sync.aligned.m16n8k8.row.col.f32.tf32.tf32.f32 "
        "{%0,%1,%2,%3}, {%4,%5,%6,%7}, {%8,%9}, {%0,%1,%2,%3};"
        : "+f"(c0), "+f"(c1), "+f"(c2), "+f"(c3)
        : "r"(a0), "r"(a1), "r"(a2), "r"(a3), "r"(b0), "r"(b1));
}

template<int D, int R, int NWM, int NWN>
__device__ __forceinline__ void run_tile(
    const float* __restrict__ x, const float* __restrict__ w,
    const float* __restrict__ bias, float* __restrict__ out,
    int off, int mt, int nt, float* sm)
{
    constexpr int BM    = R / D;
    constexpr int WM    = R / NWM;
    constexpr int WN    = BN / NWN;
    constexpr int MFRAG = WM / 16;
    constexpr int NFRAG = WN / 8;
    constexpr int ASZ   = R * LDK;
    static_assert(NWM * NWN == 8 && WM % 16 == 0 && WN % 8 == 0, "layout");

    float* const Ab[2] = {sm, sm + ASZ};
    float* const Bb[2] = {sm + 2 * ASZ_MAX, sm + 2 * ASZ_MAX + BSZ};

    const int tid  = threadIdx.x;
    const int wid  = tid >> 5;
    const int lane = tid & 31;
    const int g    = lane >> 2;
    const int tig  = lane & 3;
    const int wm   = wid % NWM;
    const int wn   = wid / NWM;
    const int b0   = mt * BM;
    const int w0   = nt * BN;

    float acc[MFRAG][NFRAG][4] = {};

    auto load_tile = [&](int t, int bufi) {
        const int k0 = t * BK;
        float* A = Ab[bufi];
        float* B = Bb[bufi];
        if constexpr (D == 1) {
            constexpr int NCH = BM * BK / 4;             // 16B chunks
            #pragma unroll
            for (int c = tid; c < NCH; c += 256) {
                const int bl = c / (BK / 4);
                const int jv = c % (BK / 4);
                const float* src = x + (size_t)(b0 + bl) * DIM + off + k0 + jv * 4;
                cp_async16((uint32_t)__cvta_generic_to_shared(A + bl * LDK + jv * 4), src);
            }
        } else {
            constexpr int NE = BM * BK * D;              // 4B scatter (de-interleave)
            #pragma unroll
            for (int e = tid; e < NE; e += 256) {
                const int bl = e / (BK * D);
                const int j  = e % (BK * D);
                const int k  = j / D;
                const int i  = j % D;
                const float* src = x + (size_t)(b0 + bl) * DIM + off + k0 * D + j;
                cp_async4((uint32_t)__cvta_generic_to_shared(A + (bl * D + i) * LDK + k), src);
            }
        }
        constexpr int NB = BK * BN / 4;
        #pragma unroll
        for (int c = tid; c < NB; c += 256) {
            const int k  = c >> 5;
            const int nv = c & 31;
            const float* src = w + (size_t)(k0 + k) * MUL + w0 + nv * 4;
            cp_async16((uint32_t)__cvta_generic_to_shared(B + k * LDB + nv * 4), src);
        }
    };

    auto compute = [&](int bufi) {
        float* A = Ab[bufi];
        float* B = Bb[bufi];
        #pragma unroll
        for (int kk = 0; kk < BK; kk += 8) {
            uint32_t afr[MFRAG][4];
            #pragma unroll
            for (int m = 0; m < MFRAG; m++) {
                const int rb = wm * WM + m * 16;
                afr[m][0] = __float_as_uint(to_tf32(A[(rb + g    ) * LDK + kk + tig    ]));
                afr[m][1] = __float_as_uint(to_tf32(A[(rb + g + 8) * LDK + kk + tig    ]));
                afr[m][2] = __float_as_uint(to_tf32(A[(rb + g    ) * LDK + kk + tig + 4]));
                afr[m][3] = __float_as_uint(to_tf32(A[(rb + g + 8) * LDK + kk + tig + 4]));
            }
            uint32_t bfr[NFRAG][2];
            #pragma unroll
            for (int n = 0; n < NFRAG; n++) {
                const int nb = wn * WN + n * 8;
                bfr[n][0] = __float_as_uint(to_tf32(B[(kk + tig    ) * LDB + nb + g]));
                bfr[n][1] = __float_as_uint(to_tf32(B[(kk + tig + 4) * LDB + nb + g]));
            }
            #pragma unroll
            for (int m = 0; m < MFRAG; m++)
                #pragma unroll
                for (int n = 0; n < NFRAG; n++)
                    mma_tf32(acc[m][n][0], acc[m][n][1], acc[m][n][2], acc[m][n][3],
                             afr[m][0], afr[m][1], afr[m][2], afr[m][3],
                             bfr[n][0], bfr[n][1]);
        }
    };

    constexpr int NK = MUL / BK;     // 32
    load_tile(0, 0);
    cp_commit();
    for (int t = 0; t < NK; t++) {
        if (t + 1 < NK) load_tile(t + 1, (t + 1) & 1);
        cp_commit();
        cp_wait1();
        __syncthreads();
        compute(t & 1);
        __syncthreads();
    }

    #pragma unroll
    for (int m = 0; m < MFRAG; m++) {
        #pragma unroll
        for (int half = 0; half < 2; half++) {
            const int row = wm * WM + m * 16 + g + half * 8;
            const int b   = b0 + row / D;
            const int i   = row % D;
            float* orow = out + (size_t)b * DIM + off + i;
            #pragma unroll
            for (int n = 0; n < NFRAG; n++) {
                const int col = wn * WN + n * 8 + 2 * tig;
                #pragma unroll
                for (int e = 0; e < 2; e++) {
                    const int wc = w0 + col + e;
                    float v = acc[m][n][half * 2 + e] * PW;
                    if (D == 1) v += bias[wc];
                    orow[(size_t)wc * D] = v;
                }
            }
        }
    }
}

// Block ranges: D=1 tile 128x128 -> 32*4 = 128 blocks
//               D=3 tile  96x128 -> 128*4 = 512 blocks
//               D=5 tile  80x128 -> 256*4 = 1024 blocks
static constexpr int NB0 = (BATCH / 128) * (MUL / BN);   // 128
static constexpr int NB1 = (BATCH / 32)  * (MUL / BN);   // 512
static constexpr int NB2 = (BATCH / 16)  * (MUL / BN);   // 1024

__global__ __launch_bounds__(256, 2) void fused_irrep_kernel(
    const float* __restrict__ x,
    const float* __restrict__ w0, const float* __restrict__ w1,
    const float* __restrict__ w2, const float* __restrict__ b0,
    float* __restrict__ out)
{
    __shared__ __align__(16) float sm[SM_FLOATS];
    const int bx = blockIdx.x;
    if (bx < NB0) {
        run_tile<1, 128, 2, 4>(x, w0, b0, out, 0,    bx >> 2, bx & 3, sm);
    } else if (bx < NB0 + NB1) {
        const int i = bx - NB0;
        run_tile<3,  96, 2, 4>(x, w1, b0, out, 512,  i >> 2, i & 3, sm);
    } else {
        const int i = bx - NB0 - NB1;
        run_tile<5,  80, 1, 8>(x, w2, b0, out, 2048, i >> 2, i & 3, sm);
    }
}

extern "C" void kernel_launch(void* const* d_in, const int* in_sizes, int n_in,
                              void* d_out, int out_size)
{
    const float* x  = (const float*)d_in[0];
    const float* w0 = (const float*)d_in[1];
    const float* w1 = (const float*)d_in[2];
    const float* w2 = (const float*)d_in[3];
    const float* b0 = (const float*)d_in[4];
    float* out = (float*)d_out;

    fused_irrep_kernel<<<NB0 + NB1 + NB2, 256>>>(x, w0, w1, w2, b0, out);
}